// round 2
// baseline (speedup 1.0000x reference)
#include <cuda_runtime.h>
#include <math.h>

// Problem constants
#define BB   8
#define QQ   2048
#define KKK  2048
#define FF   512
#define FVV  512
#define MQ   16      // q rows per CTA
#define NK   32      // k cols per tile
#define NTHREADS 256

__device__ int g_mask_is_int32;

// Probe mask dtype: int32-encoded bools have bytes 1..3 of every element == 0.
__global__ void detect_mask_kernel(const unsigned char* am){
    unsigned int nz = 0;
    #pragma unroll 8
    for (int i = 0; i < 1024; i++){
        nz |= am[4*i+1] | am[4*i+2] | am[4*i+3];
    }
    g_mask_is_int32 = (nz == 0u) ? 1 : 0;
}

// ---- packed f32x2 helpers (Blackwell FFMA2 path, PTX-only) ----
__device__ __forceinline__ unsigned long long pk2(float x, float y){
    unsigned long long r; asm("mov.b64 %0, {%1,%2};" : "=l"(r) : "f"(x), "f"(y)); return r;
}
__device__ __forceinline__ float2 upk2(unsigned long long a){
    float2 f; asm("mov.b64 {%0,%1}, %2;" : "=f"(f.x), "=f"(f.y) : "l"(a)); return f;
}
__device__ __forceinline__ void ffma2(unsigned long long &d, unsigned long long a, unsigned long long b){
    asm("fma.rn.f32x2 %0, %1, %2, %0;" : "+l"(d) : "l"(a), "l"(b));
}
__device__ __forceinline__ unsigned long long fmul2(unsigned long long a, unsigned long long b){
    unsigned long long r; asm("mul.rn.f32x2 %0, %1, %2;" : "=l"(r) : "l"(a), "l"(b)); return r;
}
__device__ __forceinline__ unsigned long long fadd2(unsigned long long a, unsigned long long b){
    unsigned long long r; asm("add.rn.f32x2 %0, %1, %2;" : "=l"(r) : "l"(a), "l"(b)); return r;
}

// Flash-style single pass:
//   O   = sum_{k, !attn_mask} exp(s_k - m) * v_k    (rescaled online)
//   l   = sum_{k (ALL)}       exp(s_k - m)          (mask is post-softmax!)
//   D   = sum_{k, !attn_mask} d_k * v_k             (d_k = alibi ? 0 : dist*bias; fp32, no rescale)
//   out = O / l - D
__global__ void __launch_bounds__(NTHREADS, 1)
attn_alibi_kernel(const float* __restrict__ q, const float* __restrict__ k,
                  const float* __restrict__ v, const float* __restrict__ cq,
                  const float* __restrict__ ck,
                  const unsigned char* __restrict__ am,
                  const unsigned char* __restrict__ al,
                  const float* __restrict__ bias,
                  float* __restrict__ out)
{
    extern __shared__ char smem_raw[];
    float* k_s  = (float*)smem_raw;            // NK*FF
    float* v_s  = k_s + NK*FF;                 // NK*FVV
    float* e_s  = v_s + NK*FVV;                // MQ*NK (raw exp values)
    float* d_s  = e_s + MQ*NK;                 // MQ*NK (scaled distances, alibi applied)
    float* ck_s = d_s + MQ*NK;                 // NK*2
    float* cq_s = ck_s + NK*2;                 // MQ*2
    unsigned int* am_s = (unsigned int*)(cq_s + MQ*2);  // MQ*NK bool-bytes as 128 uints
    unsigned int* al_s = am_s + (MQ*NK/4);

    const int t = threadIdx.x;
    const int r = t >> 4;          // q row within tile (0..15)
    const int j = t & 15;          // f-slice / output-column group (0..15)
    const int b  = blockIdx.x / (QQ / MQ);
    const int q0 = (blockIdx.x % (QQ / MQ)) * MQ;
    const int mask_i32 = g_mask_is_int32;      // uniform

    // q slice into registers (thread owns f in {4j + 64*ii + u}), packed as f32x2
    unsigned long long qq[16];
    {
        const float4* qp = (const float4*)(q + ((size_t)b*QQ + q0 + r)*FF);
        #pragma unroll
        for (int ii = 0; ii < 8; ii++){
            float4 x = qp[j + 16*ii];
            qq[2*ii]   = pk2(x.x, x.y);
            qq[2*ii+1] = pk2(x.z, x.w);
        }
    }
    if (t < MQ*2) cq_s[t] = cq[((size_t)b*QQ + q0)*2 + t];
    const float bias_scale = __ldg(bias);
    const float scale = rsqrtf((float)FF);

    unsigned long long Oa[16], Da[16];
    #pragma unroll
    for (int i = 0; i < 16; i++){ Oa[i] = 0ull; Da[i] = 0ull; }
    float m_run = -INFINITY, l_run = 0.f;

    for (int k0 = 0; k0 < KKK; k0 += NK){
        __syncthreads();   // protect smem from previous iteration's readers
        // ---- tile loads (coalesced float4) ----
        {
            const float4* kp = (const float4*)(k + ((size_t)b*KKK + k0)*FF);
            const float4* vp = (const float4*)(v + ((size_t)b*KKK + k0)*FVV);
            float4* ks4 = (float4*)k_s; float4* vs4 = (float4*)v_s;
            #pragma unroll
            for (int i = 0; i < 16; i++){
                ks4[t + 256*i] = kp[t + 256*i];
                vs4[t + 256*i] = vp[t + 256*i];
            }
        }
        if (t < NK*2) ck_s[t] = ck[((size_t)b*KKK + k0)*2 + t];
        // masks: 16 rows x 32 cols each; pack 4 bool-bytes per uint in smem.
        {
            int tt = (t < 128) ? t : (t - 128);
            int rr = tt >> 3, w = tt & 7;                       // word w covers cols 4w..4w+3
            const unsigned char* mp = (t < 128) ? am : al;
            unsigned int* ms = (t < 128) ? am_s : al_s;
            size_t elem = ((size_t)b*QQ + q0 + rr)*KKK + k0 + 4*w;
            unsigned int word;
            if (mask_i32){
                int4 x = *(const int4*)((const int*)mp + elem);
                word  = (x.x ? 0x01u : 0u) | (x.y ? 0x0100u : 0u)
                      | (x.z ? 0x010000u : 0u) | (x.w ? 0x01000000u : 0u);
            } else {
                word = *(const unsigned int*)(mp + elem);
            }
            ms[rr*8 + w] = word;
        }
        __syncthreads();

        // ---- S = (q . k^T) * scale : per-thread partial dot + 16-lane butterfly ----
        float sreg[NK];
        #pragma unroll
        for (int c = 0; c < NK; c++){
            const float4* krow = (const float4*)(k_s + c*FF);
            unsigned long long a0 = 0ull, a1 = 0ull;
            #pragma unroll
            for (int ii = 0; ii < 8; ii++){
                float4 kv = krow[j + 16*ii];
                ffma2(a0, qq[2*ii],   pk2(kv.x, kv.y));
                ffma2(a1, qq[2*ii+1], pk2(kv.z, kv.w));
            }
            float2 s2 = upk2(fadd2(a0, a1));
            float s = s2.x + s2.y;
            s += __shfl_xor_sync(0xffffffffu, s, 1);
            s += __shfl_xor_sync(0xffffffffu, s, 2);
            s += __shfl_xor_sync(0xffffffffu, s, 4);
            s += __shfl_xor_sync(0xffffffffu, s, 8);
            sreg[c] = s * scale;
        }

        // ---- online softmax bookkeeping ----
        float mt = sreg[0];
        #pragma unroll
        for (int c = 1; c < NK; c++) mt = fmaxf(mt, sreg[c]);
        float m_new = fmaxf(m_run, mt);
        float alpha = __expf(m_run - m_new);   // first tile: exp(-inf)=0
        l_run *= alpha;
        {
            unsigned long long ap = pk2(alpha, alpha);
            #pragma unroll
            for (int i = 0; i < 16; i++) Oa[i] = fmul2(Oa[i], ap);
        }
        m_run = m_new;

        // exp + distance: distributed 2 columns per thread (no redundant MUFU)
        const unsigned char* alb = (const unsigned char*)al_s;
        #pragma unroll
        for (int cc = 0; cc < 2; cc++){
            int c = j + 16*cc;
            e_s[r*NK + c] = __expf(sreg[c] - m_new);
            float dx = cq_s[2*r]   - ck_s[2*c];
            float dy = cq_s[2*r+1] - ck_s[2*c+1];
            float dd = sqrtf(dx*dx + dy*dy) * bias_scale;
            d_s[r*NK + c] = alb[r*NK + c] ? 0.f : dd;
        }
        __syncthreads();

        // l accumulates over ALL columns (mask is applied post-softmax)
        float lt = 0.f;
        #pragma unroll
        for (int c = 0; c < NK; c++) lt += e_s[r*NK + c];
        l_run += lt;

        // ---- PV / DV accumulation (packed FFMA2, V float4 reused for both) ----
        const unsigned char* amb = (const unsigned char*)am_s;
        #pragma unroll 4
        for (int c = 0; c < NK; c++){
            bool msk = amb[r*NK + c] != 0;
            float w1 = msk ? 0.f : e_s[r*NK + c];
            float w2 = msk ? 0.f : d_s[r*NK + c];
            unsigned long long w1p = pk2(w1, w1);
            unsigned long long w2p = pk2(w2, w2);
            const float4* vrow = (const float4*)(v_s + c*FVV);
            #pragma unroll
            for (int ii = 0; ii < 8; ii++){
                float4 vv = vrow[j + 16*ii];
                unsigned long long v01 = pk2(vv.x, vv.y);
                unsigned long long v23 = pk2(vv.z, vv.w);
                ffma2(Oa[2*ii],   w1p, v01);
                ffma2(Oa[2*ii+1], w1p, v23);
                ffma2(Da[2*ii],   w2p, v01);
                ffma2(Da[2*ii+1], w2p, v23);
            }
        }
    }

    // ---- epilogue: out = O / l - D ----
    float inv_l = 1.f / l_run;
    float4* op = (float4*)(out + ((size_t)b*QQ + q0 + r)*FVV);
    #pragma unroll
    for (int ii = 0; ii < 8; ii++){
        float2 o0 = upk2(Oa[2*ii]),  o1 = upk2(Oa[2*ii+1]);
        float2 d0 = upk2(Da[2*ii]),  d1 = upk2(Da[2*ii+1]);
        float4 o;
        o.x = o0.x*inv_l - d0.x;
        o.y = o0.y*inv_l - d0.y;
        o.z = o1.x*inv_l - d1.x;
        o.w = o1.y*inv_l - d1.y;
        op[j + 16*ii] = o;
    }
}

extern "C" void kernel_launch(void* const* d_in, const int* in_sizes, int n_in,
                              void* d_out, int out_size)
{
    const float*         q    = (const float*)d_in[0];
    const float*         k    = (const float*)d_in[1];
    const float*         v    = (const float*)d_in[2];
    const float*         cq   = (const float*)d_in[3];
    const float*         ck   = (const float*)d_in[4];
    const unsigned char* am   = (const unsigned char*)d_in[5];
    const unsigned char* al   = (const unsigned char*)d_in[6];
    const float*         bias = (const float*)d_in[7];
    float*               out  = (float*)d_out;

    detect_mask_kernel<<<1, 1>>>(am);

    const int smem_bytes = (NK*FF + NK*FVV + MQ*NK*2 + NK*2 + MQ*2) * (int)sizeof(float)
                         + MQ*NK*2;   // two byte masks
    cudaFuncSetAttribute(attn_alibi_kernel,
                         cudaFuncAttributeMaxDynamicSharedMemorySize, smem_bytes);
    attn_alibi_kernel<<<BB*(QQ/MQ), NTHREADS, smem_bytes>>>(q, k, v, cq, ck, am, al, bias, out);
}

// round 3
// speedup vs baseline: 1.0010x; 1.0010x over previous
#include <cuda_runtime.h>
#include <math.h>

// Problem constants
#define BB   8
#define QQ   2048
#define KKK  2048
#define FF   512
#define FVV  512
#define MQ   16      // q rows per CTA
#define NK   32      // k cols per tile
#define NTHREADS 256

__device__ int g_mask_is_int32;

// Probe mask dtype: int32-encoded bools have bytes 1..3 of every element == 0.
__global__ void detect_mask_kernel(const unsigned char* am){
    unsigned int nz = 0;
    #pragma unroll 8
    for (int i = 0; i < 1024; i++){
        nz |= am[4*i+1] | am[4*i+2] | am[4*i+3];
    }
    g_mask_is_int32 = (nz == 0u) ? 1 : 0;
}

// ---- packed f32x2 helpers (Blackwell FFMA2 path, PTX-only) ----
__device__ __forceinline__ unsigned long long pk2(float x, float y){
    unsigned long long r; asm("mov.b64 %0, {%1,%2};" : "=l"(r) : "f"(x), "f"(y)); return r;
}
__device__ __forceinline__ float2 upk2(unsigned long long a){
    float2 f; asm("mov.b64 {%0,%1}, %2;" : "=f"(f.x), "=f"(f.y) : "l"(a)); return f;
}
__device__ __forceinline__ void ffma2(unsigned long long &d, unsigned long long a, unsigned long long b){
    asm("fma.rn.f32x2 %0, %1, %2, %0;" : "+l"(d) : "l"(a), "l"(b));
}
__device__ __forceinline__ unsigned long long fmul2(unsigned long long a, unsigned long long b){
    unsigned long long r; asm("mul.rn.f32x2 %0, %1, %2;" : "=l"(r) : "l"(a), "l"(b)); return r;
}
__device__ __forceinline__ unsigned long long fadd2(unsigned long long a, unsigned long long b){
    unsigned long long r; asm("add.rn.f32x2 %0, %1, %2;" : "=l"(r) : "l"(a), "l"(b)); return r;
}

// Flash-style single pass:
//   O   = sum_{k, !attn_mask} exp(s_k - m) * v_k    (rescaled online)
//   l   = sum_{k (ALL)}       exp(s_k - m)          (mask is post-softmax!)
//   D   = sum_{k, !attn_mask} d_k * v_k             (d_k = alibi ? 0 : dist*bias; fp32, no rescale)
//   out = O / l - D
__global__ void __launch_bounds__(NTHREADS, 1)
attn_alibi_kernel(const float* __restrict__ q, const float* __restrict__ k,
                  const float* __restrict__ v, const float* __restrict__ cq,
                  const float* __restrict__ ck,
                  const unsigned char* __restrict__ am,
                  const unsigned char* __restrict__ al,
                  const float* __restrict__ bias,
                  float* __restrict__ out)
{
    extern __shared__ char smem_raw[];
    float* k_s  = (float*)smem_raw;            // NK*FF
    float* v_s  = k_s + NK*FF;                 // NK*FVV
    float* e_s  = v_s + NK*FVV;                // MQ*NK (raw exp values)
    float* d_s  = e_s + MQ*NK;                 // MQ*NK (scaled distances, alibi applied)
    float* ck_s = d_s + MQ*NK;                 // NK*2
    float* cq_s = ck_s + NK*2;                 // MQ*2
    unsigned int* am_s = (unsigned int*)(cq_s + MQ*2);  // MQ*NK bool-bytes as 128 uints
    unsigned int* al_s = am_s + (MQ*NK/4);

    const int t = threadIdx.x;
    const int r = t >> 4;          // q row within tile (0..15)
    const int j = t & 15;          // f-slice / output-column group (0..15)
    const int b  = blockIdx.x / (QQ / MQ);
    const int q0 = (blockIdx.x % (QQ / MQ)) * MQ;
    const int mask_i32 = g_mask_is_int32;      // uniform

    // q slice into registers (thread owns f in {4j + 64*ii + u}), packed as f32x2
    unsigned long long qq[16];
    {
        const float4* qp = (const float4*)(q + ((size_t)b*QQ + q0 + r)*FF);
        #pragma unroll
        for (int ii = 0; ii < 8; ii++){
            float4 x = qp[j + 16*ii];
            qq[2*ii]   = pk2(x.x, x.y);
            qq[2*ii+1] = pk2(x.z, x.w);
        }
    }
    if (t < MQ*2) cq_s[t] = cq[((size_t)b*QQ + q0)*2 + t];
    const float bias_scale = __ldg(bias);
    const float scale = rsqrtf((float)FF);

    unsigned long long Oa[16], Da[16];
    #pragma unroll
    for (int i = 0; i < 16; i++){ Oa[i] = 0ull; Da[i] = 0ull; }
    float m_run = -INFINITY, l_run = 0.f;

    for (int k0 = 0; k0 < KKK; k0 += NK){
        __syncthreads();   // protect smem from previous iteration's readers
        // ---- tile loads (coalesced float4) ----
        {
            const float4* kp = (const float4*)(k + ((size_t)b*KKK + k0)*FF);
            const float4* vp = (const float4*)(v + ((size_t)b*KKK + k0)*FVV);
            float4* ks4 = (float4*)k_s; float4* vs4 = (float4*)v_s;
            #pragma unroll
            for (int i = 0; i < 16; i++){
                ks4[t + 256*i] = kp[t + 256*i];
                vs4[t + 256*i] = vp[t + 256*i];
            }
        }
        if (t < NK*2) ck_s[t] = ck[((size_t)b*KKK + k0)*2 + t];
        // masks: 16 rows x 32 cols each; pack 4 bool-bytes per uint in smem.
        {
            int tt = (t < 128) ? t : (t - 128);
            int rr = tt >> 3, w = tt & 7;                       // word w covers cols 4w..4w+3
            const unsigned char* mp = (t < 128) ? am : al;
            unsigned int* ms = (t < 128) ? am_s : al_s;
            size_t elem = ((size_t)b*QQ + q0 + rr)*KKK + k0 + 4*w;
            unsigned int word;
            if (mask_i32){
                int4 x = *(const int4*)((const int*)mp + elem);
                word  = (x.x ? 0x01u : 0u) | (x.y ? 0x0100u : 0u)
                      | (x.z ? 0x010000u : 0u) | (x.w ? 0x01000000u : 0u);
            } else {
                word = *(const unsigned int*)(mp + elem);
            }
            ms[rr*8 + w] = word;
        }
        __syncthreads();

        // ---- S = (q . k^T) * scale : per-thread partial dot + 16-lane butterfly ----
        float sreg[NK];
        #pragma unroll
        for (int c = 0; c < NK; c++){
            const float4* krow = (const float4*)(k_s + c*FF);
            unsigned long long a0 = 0ull, a1 = 0ull;
            #pragma unroll
            for (int ii = 0; ii < 8; ii++){
                float4 kv = krow[j + 16*ii];
                ffma2(a0, qq[2*ii],   pk2(kv.x, kv.y));
                ffma2(a1, qq[2*ii+1], pk2(kv.z, kv.w));
            }
            float2 s2 = upk2(fadd2(a0, a1));
            float s = s2.x + s2.y;
            s += __shfl_xor_sync(0xffffffffu, s, 1);
            s += __shfl_xor_sync(0xffffffffu, s, 2);
            s += __shfl_xor_sync(0xffffffffu, s, 4);
            s += __shfl_xor_sync(0xffffffffu, s, 8);
            sreg[c] = s * scale;
        }

        // ---- online softmax bookkeeping ----
        float mt = sreg[0];
        #pragma unroll
        for (int c = 1; c < NK; c++) mt = fmaxf(mt, sreg[c]);
        float m_new = fmaxf(m_run, mt);
        float alpha = __expf(m_run - m_new);   // first tile: exp(-inf)=0
        l_run *= alpha;
        {
            unsigned long long ap = pk2(alpha, alpha);
            #pragma unroll
            for (int i = 0; i < 16; i++) Oa[i] = fmul2(Oa[i], ap);
        }
        m_run = m_new;

        // exp + distance: distributed 2 columns per thread (no redundant MUFU)
        const unsigned char* alb = (const unsigned char*)al_s;
        #pragma unroll
        for (int cc = 0; cc < 2; cc++){
            int c = j + 16*cc;
            e_s[r*NK + c] = __expf(sreg[c] - m_new);
            float dx = cq_s[2*r]   - ck_s[2*c];
            float dy = cq_s[2*r+1] - ck_s[2*c+1];
            float dd = sqrtf(dx*dx + dy*dy) * bias_scale;
            d_s[r*NK + c] = alb[r*NK + c] ? 0.f : dd;
        }
        __syncthreads();

        // l accumulates over ALL columns (mask is applied post-softmax)
        float lt = 0.f;
        #pragma unroll
        for (int c = 0; c < NK; c++) lt += e_s[r*NK + c];
        l_run += lt;

        // ---- PV / DV accumulation (packed FFMA2, V float4 reused for both) ----
        const unsigned char* amb = (const unsigned char*)am_s;
        #pragma unroll 4
        for (int c = 0; c < NK; c++){
            bool msk = amb[r*NK + c] != 0;
            float w1 = msk ? 0.f : e_s[r*NK + c];
            float w2 = msk ? 0.f : d_s[r*NK + c];
            unsigned long long w1p = pk2(w1, w1);
            unsigned long long w2p = pk2(w2, w2);
            const float4* vrow = (const float4*)(v_s + c*FVV);
            #pragma unroll
            for (int ii = 0; ii < 8; ii++){
                float4 vv = vrow[j + 16*ii];
                unsigned long long v01 = pk2(vv.x, vv.y);
                unsigned long long v23 = pk2(vv.z, vv.w);
                ffma2(Oa[2*ii],   w1p, v01);
                ffma2(Oa[2*ii+1], w1p, v23);
                ffma2(Da[2*ii],   w2p, v01);
                ffma2(Da[2*ii+1], w2p, v23);
            }
        }
    }

    // ---- epilogue: out = O / l - D ----
    float inv_l = 1.f / l_run;
    float4* op = (float4*)(out + ((size_t)b*QQ + q0 + r)*FVV);
    #pragma unroll
    for (int ii = 0; ii < 8; ii++){
        float2 o0 = upk2(Oa[2*ii]),  o1 = upk2(Oa[2*ii+1]);
        float2 d0 = upk2(Da[2*ii]),  d1 = upk2(Da[2*ii+1]);
        float4 o;
        o.x = o0.x*inv_l - d0.x;
        o.y = o0.y*inv_l - d0.y;
        o.z = o1.x*inv_l - d1.x;
        o.w = o1.y*inv_l - d1.y;
        op[j + 16*ii] = o;
    }
}

extern "C" void kernel_launch(void* const* d_in, const int* in_sizes, int n_in,
                              void* d_out, int out_size)
{
    const float*         q    = (const float*)d_in[0];
    const float*         k    = (const float*)d_in[1];
    const float*         v    = (const float*)d_in[2];
    const float*         cq   = (const float*)d_in[3];
    const float*         ck   = (const float*)d_in[4];
    const unsigned char* am   = (const unsigned char*)d_in[5];
    const unsigned char* al   = (const unsigned char*)d_in[6];
    const float*         bias = (const float*)d_in[7];
    float*               out  = (float*)d_out;

    detect_mask_kernel<<<1, 1>>>(am);

    const int smem_bytes = (NK*FF + NK*FVV + MQ*NK*2 + NK*2 + MQ*2) * (int)sizeof(float)
                         + MQ*NK*2;   // two byte masks
    cudaFuncSetAttribute(attn_alibi_kernel,
                         cudaFuncAttributeMaxDynamicSharedMemorySize, smem_bytes);
    attn_alibi_kernel<<<BB*(QQ/MQ), NTHREADS, smem_bytes>>>(q, k, v, cq, ck, am, al, bias, out);
}

// round 4
// speedup vs baseline: 8.7159x; 8.7070x over previous
#include <cuda_runtime.h>
#include <cuda_bf16.h>
#include <math.h>

#define BB   8
#define QQ   2048
#define KK2  2048
#define FF   512
#define FVV  512
#define NTHREADS 256

// ---------------- scratch (device globals; no runtime allocation) ----------------
// A-blob (64x64): [ks 8][mf 4][lane 32][reg 4]; element (row = mf*16+g+8*rh, col = ks*8+t+4*j), reg = rh+2*j
// B-blob (64x64): [ks 8][nf 8][lane 32][reg 2]; element (k = ks*8+t+4*j, n = nf*8+g), reg = j
__device__ float g_Qp[8388608];                  // (b, qt32, ft8) A-blobs   33.5MB
__device__ float g_Kp[8388608];                  // (b, kt32, ft8) B-blobs   33.5MB
__device__ float g_Vp[8388608];                  // (b, fvt8, kt32) B-blobs  33.5MB
__device__ float g_Wp[33554432];                 // (b, qt32, kt32) A-blobs  134MB
__device__ __nv_bfloat16 g_E[33554432];          // exp(logits) row-major    67MB
__device__ float g_linv[BB*QQ];
__device__ int   g_mask_is_int32;

// ---------------- helpers ----------------
__device__ __forceinline__ unsigned to_tf32(float f){
    unsigned u; asm("cvt.rna.tf32.f32 %0, %1;" : "=r"(u) : "f"(f)); return u;
}
__device__ __forceinline__ void mma_tf32(float c[4], const unsigned* a, const unsigned* b){
    asm volatile("mma.sync.aligned.m16n8k8.row.col.f32.tf32.tf32.f32 "
        "{%0,%1,%2,%3}, {%4,%5,%6,%7}, {%8,%9}, {%0,%1,%2,%3};"
        : "+f"(c[0]), "+f"(c[1]), "+f"(c[2]), "+f"(c[3])
        : "r"(a[0]), "r"(a[1]), "r"(a[2]), "r"(a[3]), "r"(b[0]), "r"(b[1]));
}
// exp on the FMA pipe: 2^(x*log2e), deg-5 poly (rel err ~2e-7 for |x| < 15)
__device__ __forceinline__ float fexp(float x){
    float t = x * 1.4426950408889634f;
    float r = rintf(t);
    float f = t - r;
    float p = 1.3333558146428443e-3f;
    p = fmaf(p, f, 9.618129107628477e-3f);
    p = fmaf(p, f, 5.550410866482158e-2f);
    p = fmaf(p, f, 2.402265069591007e-1f);
    p = fmaf(p, f, 6.931471805599453e-1f);
    p = fmaf(p, f, 1.0f);
    return __int_as_float(((int)r + 127) << 23) * p;
}
// rsqrt on FMA pipe, 2 Newton steps (~1e-6 rel)
__device__ __forceinline__ float frsqrt2(float x){
    float y = __int_as_float(0x5f3759df - (__float_as_int(x) >> 1));
    y = y * (1.5f - 0.5f * x * y * y);
    y = y * (1.5f - 0.5f * x * y * y);
    return y;
}
__device__ __forceinline__ unsigned sm_u32(const void* p){
    return (unsigned)__cvta_generic_to_shared(p);
}
#define CP_ASYNC16(sm, gp) asm volatile("cp.async.cg.shared.global [%0], [%1], 16;" :: "r"(sm), "l"(gp))
#define CP_COMMIT()        asm volatile("cp.async.commit_group;" ::: "memory")

// ---------------- mask dtype probe ----------------
__global__ void detect_mask_kernel(const unsigned char* am){
    unsigned nz = 0;
    #pragma unroll 8
    for (int i = 0; i < 1024; i++) nz |= am[4*i+1] | am[4*i+2] | am[4*i+3];
    g_mask_is_int32 = (nz == 0u) ? 1 : 0;
}

// ---------------- prep Q -> A-fragment-major tf32 ----------------
__global__ void __launch_bounds__(NTHREADS) prep_q_kernel(const float* __restrict__ q){
    int w = blockIdx.x * 8 + (threadIdx.x >> 5);
    int lane = threadIdx.x & 31, g = lane >> 2, t = lane & 3;
    int mf = w & 3, fs = (w>>2)&7, ft = (w>>5)&7, qt = (w>>8)&31, b = w>>13;
    unsigned rr[4];
    #pragma unroll
    for (int j = 0; j < 2; j++)
        #pragma unroll
        for (int rh = 0; rh < 2; rh++){
            int row = qt*64 + mf*16 + g + 8*rh;
            int col = ft*64 + fs*8 + t + 4*j;
            rr[rh + 2*j] = to_tf32(q[((size_t)(b*QQ + row))*FF + col]);
        }
    size_t blob = ((size_t)((b*32 + qt)*8 + ft))*4096;
    *(uint4*)(g_Qp + blob + ((fs*4 + mf)*32 + lane)*4) = make_uint4(rr[0],rr[1],rr[2],rr[3]);
}

// ---------------- prep K -> B-fragment-major tf32 ----------------
__global__ void __launch_bounds__(NTHREADS) prep_k_kernel(const float* __restrict__ k){
    int w = blockIdx.x * 8 + (threadIdx.x >> 5);
    int lane = threadIdx.x & 31, g = lane >> 2, t = lane & 3;
    int nf = w & 7, fs = (w>>3)&7, ft = (w>>6)&7, kt = (w>>9)&31, b = w>>14;
    unsigned rr[2];
    #pragma unroll
    for (int j = 0; j < 2; j++){
        int kn = kt*64 + nf*8 + g;
        int f  = ft*64 + fs*8 + t + 4*j;
        rr[j] = to_tf32(k[((size_t)(b*KK2 + kn))*FF + f]);
    }
    size_t blob = ((size_t)((b*32 + kt)*8 + ft))*4096;
    *(uint2*)(g_Kp + blob + ((fs*8 + nf)*32 + lane)*2) = make_uint2(rr[0], rr[1]);
}

// ---------------- prep V -> B-fragment-major tf32 (contraction = seq-k, n = fv) ----------------
__global__ void __launch_bounds__(NTHREADS) prep_v_kernel(const float* __restrict__ v){
    int w = blockIdx.x * 8 + (threadIdx.x >> 5);
    int lane = threadIdx.x & 31, g = lane >> 2, t = lane & 3;
    int nf = w & 7, ks = (w>>3)&7, kt = (w>>6)&31, fvt = (w>>11)&7, b = w>>14;
    unsigned rr[2];
    #pragma unroll
    for (int j = 0; j < 2; j++){
        int kk = kt*64 + ks*8 + t + 4*j;
        int fv = fvt*64 + nf*8 + g;
        rr[j] = to_tf32(v[((size_t)(b*KK2 + kk))*FVV + fv]);
    }
    size_t blob = ((size_t)((b*8 + fvt)*32 + kt))*4096;
    *(uint2*)(g_Vp + blob + ((ks*8 + nf)*32 + lane)*2) = make_uint2(rr[0], rr[1]);
}

// ---------------- pass1: S = QK^T * scale; E = exp(S); linv = 1/rowsum ----------------
__global__ void __launch_bounds__(NTHREADS, 1) pass1_kernel(void){
    extern __shared__ float smem[];
    float* smQ = smem;              // 8 blobs * 4096 = 32768 floats (128KB)
    float* l_s = smem + 32768;      // 8 warps * 64 rows

    int tid = threadIdx.x, lane = tid & 31, wc = tid >> 5;
    int g = lane >> 2, t = lane & 3;
    int b = blockIdx.x >> 5, qt = blockIdx.x & 31;
    const float SCALE = 0.044194173824159216f;  // 1/sqrt(512)

    {   // stage all 8 Q blobs for this q-tile (reused by every warp, every kb)
        const float4* src = (const float4*)(g_Qp + ((size_t)((b*32 + qt)*8))*4096);
        float4* dst = (float4*)smQ;
        #pragma unroll
        for (int i = 0; i < 32; i++) dst[tid + 256*i] = src[tid + 256*i];
    }
    __syncthreads();

    float rsl[4][2];
    #pragma unroll
    for (int a=0;a<4;a++){ rsl[a][0]=0.f; rsl[a][1]=0.f; }

    #pragma unroll 1
    for (int kb = 0; kb < 8; kb++){
        int kt = kb*4 + (wc >> 1);
        int nb = (wc & 1) * 4;

        float C[4][4][4];
        #pragma unroll
        for (int a=0;a<4;a++)
            #pragma unroll
            for (int bb=0;bb<4;bb++)
                #pragma unroll
                for (int c=0;c<4;c++) C[a][bb][c]=0.f;

        #pragma unroll 1
        for (int ft = 0; ft < 8; ft++){
            const float* As = smQ + ft*4096;
            const float* Bb = g_Kp + ((size_t)((b*32 + kt)*8 + ft))*4096;
            #pragma unroll
            for (int fs = 0; fs < 8; fs++){
                uint4 Af[4];
                #pragma unroll
                for (int mf=0; mf<4; mf++)
                    Af[mf] = *(const uint4*)(As + ((fs*4 + mf)*32 + lane)*4);
                uint2 Bf[4];
                #pragma unroll
                for (int nf=0; nf<4; nf++)
                    Bf[nf] = *(const uint2*)(Bb + ((fs*8 + nb + nf)*32 + lane)*2);
                #pragma unroll
                for (int mf=0; mf<4; mf++)
                    #pragma unroll
                    for (int nf=0; nf<4; nf++)
                        mma_tf32(C[mf][nf], (const unsigned*)&Af[mf], (const unsigned*)&Bf[nf]);
            }
        }

        // exp + E store + deterministic row-sum partials
        #pragma unroll
        for (int mf = 0; mf < 4; mf++)
            #pragma unroll
            for (int rh = 0; rh < 2; rh++){
                int row = qt*64 + mf*16 + g + 8*rh;
                float rs = 0.f;
                #pragma unroll
                for (int nf = 0; nf < 4; nf++){
                    float e0 = fexp(C[mf][nf][rh*2+0] * SCALE);
                    float e1 = fexp(C[mf][nf][rh*2+1] * SCALE);
                    rs += e0 + e1;
                    int kcol = kb*256 + wc*32 + nf*8 + 2*t;
                    size_t idx = ((size_t)(b*QQ + row))*KK2 + kcol;
                    ((__nv_bfloat162*)g_E)[idx >> 1] = __floats2bfloat162_rn(e0, e1);
                }
                rsl[mf][rh] += rs;
            }
    }

    #pragma unroll
    for (int mf = 0; mf < 4; mf++)
        #pragma unroll
        for (int rh = 0; rh < 2; rh++){
            float rs = rsl[mf][rh];
            rs += __shfl_xor_sync(0xffffffffu, rs, 1);
            rs += __shfl_xor_sync(0xffffffffu, rs, 2);
            if (t == 0) l_s[wc*64 + mf*16 + g + 8*rh] = rs;
        }
    __syncthreads();
    if (tid < 64){
        float s = 0.f;
        #pragma unroll
        for (int w = 0; w < 8; w++) s += l_s[w*64 + tid];
        g_linv[b*QQ + qt*64 + tid] = 1.0f / s;
    }
}

// ---------------- buildW: W = attn?0:(E*linv - alibi?0:dist*bias), A-fragment tf32 ----------------
__global__ void __launch_bounds__(NTHREADS) buildW_kernel(
    const float* __restrict__ cq, const float* __restrict__ ck,
    const unsigned char* __restrict__ am, const unsigned char* __restrict__ al,
    const float* __restrict__ bias)
{
    int w = blockIdx.x * 8 + (threadIdx.x >> 5);
    int lane = threadIdx.x & 31, g = lane >> 2, t = lane & 3;
    int mf = w & 3, kt = (w>>2)&31, qt = (w>>7)&31, b = w>>12;
    const int m32 = g_mask_is_int32;
    const float bsc = __ldg(bias);

    int qrow[2]; float li[2]; float2 cqv[2];
    #pragma unroll
    for (int rh = 0; rh < 2; rh++){
        qrow[rh] = qt*64 + mf*16 + g + 8*rh;
        li[rh]   = g_linv[b*QQ + qrow[rh]];
        cqv[rh]  = *(const float2*)(cq + ((size_t)(b*QQ + qrow[rh]))*2);
    }
    size_t blob = ((size_t)((b*32 + qt)*32 + kt))*4096;

    #pragma unroll 1
    for (int ks = 0; ks < 8; ks++){
        unsigned o4[4];
        #pragma unroll
        for (int j = 0; j < 2; j++){
            int kcol = kt*64 + ks*8 + t + 4*j;
            float2 ckv = *(const float2*)(ck + ((size_t)(b*KK2 + kcol))*2);
            #pragma unroll
            for (int rh = 0; rh < 2; rh++){
                size_t idx = ((size_t)(b*QQ + qrow[rh]))*KK2 + kcol;
                bool amv, alv;
                if (m32){ amv = ((const int*)am)[idx] != 0; alv = ((const int*)al)[idx] != 0; }
                else    { amv = am[idx] != 0;               alv = al[idx] != 0; }
                float e  = __bfloat162float(g_E[idx]) * li[rh];
                float dx = cqv[rh].x - ckv.x, dy = cqv[rh].y - ckv.y;
                float r2 = fmaxf(dx*dx + dy*dy, 1e-30f);
                float d  = alv ? 0.f : (r2 * frsqrt2(r2) * bsc);
                float wv = amv ? 0.f : (e - d);
                o4[rh + 2*j] = to_tf32(wv);
            }
        }
        *(uint4*)(g_Wp + blob + ((ks*4 + mf)*32 + lane)*4) = make_uint4(o4[0],o4[1],o4[2],o4[3]);
    }
}

// ---------------- pass2: O = W * V (cp.async double-buffered A) ----------------
__global__ void __launch_bounds__(NTHREADS, 1) pass2_kernel(float* __restrict__ out){
    extern __shared__ float smem[];   // 2 * 4096 floats = 32KB
    int tid = threadIdx.x, lane = tid & 31, wc = tid >> 5;
    int g = lane >> 2, t = lane & 3;
    int b = blockIdx.x >> 5, qt = blockIdx.x & 31;

    float C[4][8][4];
    #pragma unroll
    for (int a=0;a<4;a++)
        #pragma unroll
        for (int n=0;n<8;n++)
            #pragma unroll
            for (int c=0;c<4;c++) C[a][n][c]=0.f;

    const float* Wbase = g_Wp + ((size_t)((b*32 + qt)*32))*4096;
    unsigned sbase = sm_u32(smem);

    {   // stage kt = 0
        const float4* src = (const float4*)(Wbase);
        #pragma unroll
        for (int i = 0; i < 4; i++)
            CP_ASYNC16(sbase + (tid + 256*i)*16, (const void*)(src + tid + 256*i));
        CP_COMMIT();
    }

    #pragma unroll 1
    for (int kt = 0; kt < 32; kt++){
        if (kt < 31){
            const float4* src = (const float4*)(Wbase + (size_t)(kt+1)*4096);
            unsigned dst = sbase + ((kt+1)&1)*16384;
            #pragma unroll
            for (int i = 0; i < 4; i++)
                CP_ASYNC16(dst + (tid + 256*i)*16, (const void*)(src + tid + 256*i));
            CP_COMMIT();
            asm volatile("cp.async.wait_group 1;" ::: "memory");
        } else {
            asm volatile("cp.async.wait_group 0;" ::: "memory");
        }
        __syncthreads();

        const float* Ab = smem + (kt&1)*4096;
        const float* Bb = g_Vp + ((size_t)((b*8 + wc)*32 + kt))*4096;
        #pragma unroll
        for (int ks = 0; ks < 8; ks++){
            uint4 Af[4];
            #pragma unroll
            for (int mf=0; mf<4; mf++)
                Af[mf] = *(const uint4*)(Ab + ((ks*4 + mf)*32 + lane)*4);
            uint2 Bf[8];
            #pragma unroll
            for (int nf=0; nf<8; nf++)
                Bf[nf] = *(const uint2*)(Bb + ((ks*8 + nf)*32 + lane)*2);
            #pragma unroll
            for (int mf=0; mf<4; mf++)
                #pragma unroll
                for (int nf=0; nf<8; nf++)
                    mma_tf32(C[mf][nf], (const unsigned*)&Af[mf], (const unsigned*)&Bf[nf]);
        }
        __syncthreads();
    }

    // epilogue: fp32 out, 8B stores (32B sectors per 8-row group)
    #pragma unroll
    for (int mf = 0; mf < 4; mf++)
        #pragma unroll
        for (int rh = 0; rh < 2; rh++){
            int row = qt*64 + mf*16 + g + 8*rh;
            float* orow = out + ((size_t)(b*QQ + row))*FVV;
            #pragma unroll
            for (int nf = 0; nf < 8; nf++){
                int fv = wc*64 + nf*8 + 2*t;
                *(float2*)(orow + fv) = make_float2(C[mf][nf][rh*2+0], C[mf][nf][rh*2+1]);
            }
        }
}

extern "C" void kernel_launch(void* const* d_in, const int* in_sizes, int n_in,
                              void* d_out, int out_size)
{
    const float*         q    = (const float*)d_in[0];
    const float*         k    = (const float*)d_in[1];
    const float*         v    = (const float*)d_in[2];
    const float*         cq   = (const float*)d_in[3];
    const float*         ck   = (const float*)d_in[4];
    const unsigned char* am   = (const unsigned char*)d_in[5];
    const unsigned char* al   = (const unsigned char*)d_in[6];
    const float*         bias = (const float*)d_in[7];
    float*               out  = (float*)d_out;

    detect_mask_kernel<<<1, 1>>>(am);
    prep_q_kernel<<<8192,  NTHREADS>>>(q);
    prep_k_kernel<<<16384, NTHREADS>>>(k);
    prep_v_kernel<<<16384, NTHREADS>>>(v);

    static int smem_set = 0;
    if (!smem_set){
        cudaFuncSetAttribute(pass1_kernel, cudaFuncAttributeMaxDynamicSharedMemorySize, 133120);
        cudaFuncSetAttribute(pass2_kernel, cudaFuncAttributeMaxDynamicSharedMemorySize, 32768);
        smem_set = 1;
    }
    pass1_kernel<<<256, NTHREADS, 133120>>>();
    buildW_kernel<<<4096, NTHREADS>>>(cq, ck, am, al, bias);
    pass2_kernel<<<256, NTHREADS, 32768>>>(out);
}

// round 5
// speedup vs baseline: 9.3744x; 1.0756x over previous
#include <cuda_runtime.h>
#include <cuda_bf16.h>
#include <math.h>

#define BB   8
#define QQ   2048
#define KK2  2048
#define FF   512
#define FVV  512
#define NTHREADS 256

// ---------------- scratch (device globals; no runtime allocation) ----------------
// bf16 A-blob (64x64): [ks4][mf4][lane32][4 b32] ; regs: r0=(g,2t..),r1=(g+8,2t..),r2=(g,2t+8..),r3=(g+8,2t+8..)
// bf16 B-blob (64x64): [ks4][nf8][lane32][2 b32] ; r0=(k=2t..,n=g), r1=(k=2t+8..,n=g)
// tf32 B-blob (64x64): [ks8][nf8][lane32][2 b32] ; r0=(k=t,n=g), r1=(k=t+4,n=g)
__device__ __align__(16) unsigned g_Qpb[4194304];     // (b, qt32, ft8) bf16 A-blobs  16.8MB
__device__ __align__(16) unsigned g_Kpb[4194304];     // (b, kt32, ft8) bf16 B-blobs  16.8MB
__device__ __align__(16) float    g_Vp [8388608];     // (b, fvt8, kt32) tf32 B-blobs 33.5MB
__device__ __align__(16) __nv_bfloat16 g_E[33554432]; // exp(logits) row-major        67MB
__device__ float g_linv[BB*QQ];
__device__ int   g_mask_is_int32;

// ---------------- helpers ----------------
__device__ __forceinline__ unsigned to_tf32(float f){
    unsigned u; asm("cvt.rna.tf32.f32 %0, %1;" : "=r"(u) : "f"(f)); return u;
}
__device__ __forceinline__ void mma_tf32(float c[4], const unsigned* a, const unsigned* b){
    asm volatile("mma.sync.aligned.m16n8k8.row.col.f32.tf32.tf32.f32 "
        "{%0,%1,%2,%3}, {%4,%5,%6,%7}, {%8,%9}, {%0,%1,%2,%3};"
        : "+f"(c[0]), "+f"(c[1]), "+f"(c[2]), "+f"(c[3])
        : "r"(a[0]), "r"(a[1]), "r"(a[2]), "r"(a[3]), "r"(b[0]), "r"(b[1]));
}
__device__ __forceinline__ void mma_bf16(float c[4], const unsigned* a, const unsigned* b){
    asm volatile("mma.sync.aligned.m16n8k16.row.col.f32.bf16.bf16.f32 "
        "{%0,%1,%2,%3}, {%4,%5,%6,%7}, {%8,%9}, {%0,%1,%2,%3};"
        : "+f"(c[0]), "+f"(c[1]), "+f"(c[2]), "+f"(c[3])
        : "r"(a[0]), "r"(a[1]), "r"(a[2]), "r"(a[3]), "r"(b[0]), "r"(b[1]));
}
// exp on the FMA pipe: 2^(x*log2e), deg-5 poly (rel err ~2e-7 for |x| < 15)
__device__ __forceinline__ float fexp(float x){
    float t = x * 1.4426950408889634f;
    float r = rintf(t);
    float f = t - r;
    float p = 1.3333558146428443e-3f;
    p = fmaf(p, f, 9.618129107628477e-3f);
    p = fmaf(p, f, 5.550410866482158e-2f);
    p = fmaf(p, f, 2.402265069591007e-1f);
    p = fmaf(p, f, 6.931471805599453e-1f);
    p = fmaf(p, f, 1.0f);
    return __int_as_float(((int)r + 127) << 23) * p;
}
// rsqrt on FMA pipe, 2 Newton steps (~1e-6 rel)
__device__ __forceinline__ float frsqrt2(float x){
    float y = __int_as_float(0x5f3759df - (__float_as_int(x) >> 1));
    y = y * (1.5f - 0.5f * x * y * y);
    y = y * (1.5f - 0.5f * x * y * y);
    return y;
}

// ---------------- mask dtype probe ----------------
__global__ void detect_mask_kernel(const unsigned char* am){
    unsigned nz = 0;
    #pragma unroll 8
    for (int i = 0; i < 1024; i++) nz |= am[4*i+1] | am[4*i+2] | am[4*i+3];
    g_mask_is_int32 = (nz == 0u) ? 1 : 0;
}

// ---------------- prep Q -> bf16 A-fragment blobs ----------------
__global__ void __launch_bounds__(NTHREADS) prep_qb_kernel(const float* __restrict__ q){
    int w = blockIdx.x * 8 + (threadIdx.x >> 5);
    int lane = threadIdx.x & 31, g = lane >> 2, t = lane & 3;
    int mf = w & 3, ks = (w>>2)&3, ft = (w>>4)&7, qt = (w>>7)&31, b = w>>12;
    unsigned rr[4];
    #pragma unroll
    for (int rh = 0; rh < 2; rh++){
        int row = qt*64 + mf*16 + g + 8*rh;
        const float* qp = q + ((size_t)(b*QQ + row))*FF + ft*64 + ks*16 + 2*t;
        float2 x0 = *(const float2*)qp;
        float2 x1 = *(const float2*)(qp + 8);
        __nv_bfloat162 h0 = __floats2bfloat162_rn(x0.x, x0.y);
        __nv_bfloat162 h1 = __floats2bfloat162_rn(x1.x, x1.y);
        rr[rh]   = *(unsigned*)&h0;
        rr[rh+2] = *(unsigned*)&h1;
    }
    size_t blob = ((size_t)((b*32 + qt)*8 + ft))*2048;
    *(uint4*)(g_Qpb + blob + ((ks*4 + mf)*32 + lane)*4) = make_uint4(rr[0],rr[1],rr[2],rr[3]);
}

// ---------------- prep K -> bf16 B-fragment blobs ----------------
__global__ void __launch_bounds__(NTHREADS) prep_kb_kernel(const float* __restrict__ k){
    int w = blockIdx.x * 8 + (threadIdx.x >> 5);
    int lane = threadIdx.x & 31, g = lane >> 2, t = lane & 3;
    int nf = w & 7, ks = (w>>3)&3, ft = (w>>5)&7, kt = (w>>8)&31, b = w>>13;
    int n = kt*64 + nf*8 + g;
    const float* kp = k + ((size_t)(b*KK2 + n))*FF + ft*64 + ks*16 + 2*t;
    float2 x0 = *(const float2*)kp;
    float2 x1 = *(const float2*)(kp + 8);
    __nv_bfloat162 h0 = __floats2bfloat162_rn(x0.x, x0.y);
    __nv_bfloat162 h1 = __floats2bfloat162_rn(x1.x, x1.y);
    size_t blob = ((size_t)((b*32 + kt)*8 + ft))*2048;
    *(uint2*)(g_Kpb + blob + ((ks*8 + nf)*32 + lane)*2) =
        make_uint2(*(unsigned*)&h0, *(unsigned*)&h1);
}

// ---------------- prep V -> tf32 B-fragment blobs (contraction = seq-k, n = fv) ----------------
__global__ void __launch_bounds__(NTHREADS) prep_v_kernel(const float* __restrict__ v){
    int w = blockIdx.x * 8 + (threadIdx.x >> 5);
    int lane = threadIdx.x & 31, g = lane >> 2, t = lane & 3;
    int nf = w & 7, ks = (w>>3)&7, kt = (w>>6)&31, fvt = (w>>11)&7, b = w>>14;
    unsigned rr[2];
    #pragma unroll
    for (int j = 0; j < 2; j++){
        int kk = kt*64 + ks*8 + t + 4*j;
        int fv = fvt*64 + nf*8 + g;
        rr[j] = to_tf32(v[((size_t)(b*KK2 + kk))*FVV + fv]);
    }
    size_t blob = ((size_t)((b*8 + fvt)*32 + kt))*4096;
    *(uint2*)(g_Vp + blob + ((ks*8 + nf)*32 + lane)*2) = make_uint2(rr[0], rr[1]);
}

// ---------------- pass1: S = QK^T * scale (bf16 mma); E = exp(S); linv = 1/rowsum ----------------
__global__ void __launch_bounds__(NTHREADS, 1) pass1_kernel(void){
    extern __shared__ unsigned smem_u[];
    unsigned* smQ = smem_u;                    // 16384 words = 64KB
    float* l_s = (float*)(smem_u + 16384);     // 8 warps * 64 rows

    int tid = threadIdx.x, lane = tid & 31, wc = tid >> 5;
    int g = lane >> 2, t = lane & 3;
    int b = blockIdx.x >> 5, qt = blockIdx.x & 31;
    const float SCALE = 0.044194173824159216f;  // 1/sqrt(512)

    {   // stage all 8 Q blobs for this q-tile
        const uint4* src = (const uint4*)(g_Qpb + ((size_t)((b*32 + qt)*8))*2048);
        uint4* dst = (uint4*)smQ;
        #pragma unroll
        for (int i = 0; i < 16; i++) dst[tid + 256*i] = src[tid + 256*i];
    }
    __syncthreads();

    float rsl[4][2];
    #pragma unroll
    for (int a=0;a<4;a++){ rsl[a][0]=0.f; rsl[a][1]=0.f; }

    #pragma unroll 1
    for (int kb = 0; kb < 8; kb++){
        int kt = kb*4 + (wc >> 1);
        int nb = (wc & 1) * 4;

        float C[4][4][4];
        #pragma unroll
        for (int a=0;a<4;a++)
            #pragma unroll
            for (int bb=0;bb<4;bb++)
                #pragma unroll
                for (int c=0;c<4;c++) C[a][bb][c]=0.f;

        #pragma unroll 1
        for (int ft = 0; ft < 8; ft++){
            const unsigned* As = smQ + ft*2048;
            const unsigned* Bb = g_Kpb + ((size_t)((b*32 + kt)*8 + ft))*2048;
            #pragma unroll
            for (int ks = 0; ks < 4; ks++){
                uint4 Af[4];
                #pragma unroll
                for (int mf=0; mf<4; mf++)
                    Af[mf] = *(const uint4*)(As + ((ks*4 + mf)*32 + lane)*4);
                uint2 Bf[4];
                #pragma unroll
                for (int nf=0; nf<4; nf++)
                    Bf[nf] = *(const uint2*)(Bb + ((ks*8 + nb + nf)*32 + lane)*2);
                #pragma unroll
                for (int mf=0; mf<4; mf++)
                    #pragma unroll
                    for (int nf=0; nf<4; nf++)
                        mma_bf16(C[mf][nf], (const unsigned*)&Af[mf], (const unsigned*)&Bf[nf]);
            }
        }

        // exp + E store + row-sum partials
        #pragma unroll
        for (int mf = 0; mf < 4; mf++)
            #pragma unroll
            for (int rh = 0; rh < 2; rh++){
                int row = qt*64 + mf*16 + g + 8*rh;
                float rs = 0.f;
                #pragma unroll
                for (int nf = 0; nf < 4; nf++){
                    float e0 = fexp(C[mf][nf][rh*2+0] * SCALE);
                    float e1 = fexp(C[mf][nf][rh*2+1] * SCALE);
                    rs += e0 + e1;
                    int kcol = kb*256 + wc*32 + nf*8 + 2*t;
                    size_t idx = ((size_t)(b*QQ + row))*KK2 + kcol;
                    ((__nv_bfloat162*)g_E)[idx >> 1] = __floats2bfloat162_rn(e0, e1);
                }
                rsl[mf][rh] += rs;
            }
    }

    #pragma unroll
    for (int mf = 0; mf < 4; mf++)
        #pragma unroll
        for (int rh = 0; rh < 2; rh++){
            float rs = rsl[mf][rh];
            rs += __shfl_xor_sync(0xffffffffu, rs, 1);
            rs += __shfl_xor_sync(0xffffffffu, rs, 2);
            if (t == 0) l_s[wc*64 + mf*16 + g + 8*rh] = rs;
        }
    __syncthreads();
    if (tid < 64){
        float s = 0.f;
        #pragma unroll
        for (int w = 0; w < 8; w++) s += l_s[w*64 + tid];
        g_linv[b*QQ + qt*64 + tid] = 1.0f / s;
    }
}

// ---------------- pass2 (fused): W built on the fly in smem; O = W*V (tf32 mma) ----------------
// W smem layout: row-major 64 x 68 (pad) floats per buffer, double-buffered.
// A-frag gather via 4x LDS.32 -> bank = (g*4+t) mod 32, conflict-free.
#define WPAD 68
__global__ void __launch_bounds__(NTHREADS, 1) pass2_kernel(
    float* __restrict__ out,
    const float* __restrict__ cq, const float* __restrict__ ck,
    const unsigned char* __restrict__ am, const unsigned char* __restrict__ al,
    const float* __restrict__ bias)
{
    extern __shared__ float smem[];   // 2 * 64*68 floats = 34816 B
    int tid = threadIdx.x, lane = tid & 31, wc = tid >> 5;
    int g = lane >> 2, t = lane & 3;
    int b = blockIdx.x >> 5, qt = blockIdx.x & 31;

    // build role: thread owns row brow (within q-tile), 16 cols starting at bc0 (within k-tile)
    const int brow = wc*8 + (lane >> 2);
    const int bc0  = (lane & 3) * 16;
    const float2 cqv = *(const float2*)(cq + ((size_t)(b*QQ + qt*64 + brow))*2);
    const float li   = g_linv[b*QQ + qt*64 + brow];
    const size_t erow = ((size_t)(b*QQ + qt*64 + brow))*KK2;
    const float bsc = __ldg(bias);
    const int m32 = g_mask_is_int32;

    float C[4][8][4];
    #pragma unroll
    for (int a=0;a<4;a++)
        #pragma unroll
        for (int n=0;n<8;n++)
            #pragma unroll
            for (int c=0;c<4;c++) C[a][n][c]=0.f;

    #pragma unroll 1
    for (int kt = 0; kt < 32; kt++){
        float* Wb = smem + (kt & 1) * (64*WPAD);

        // ---- build W tile: 2 half-batches of 8 cols to bound register pressure ----
        #pragma unroll
        for (int h = 0; h < 2; h++){
            int cb = kt*64 + bc0 + 8*h;            // global k col of first of 8
            // E: 8 bf16 = 1 uint4
            uint4 eu = *(const uint4*)(g_E + erow + cb);
            const unsigned* ew = (const unsigned*)&eu;
            // masks
            int amv[8], alv[8];
            if (m32){
                const int4* ap = (const int4*)((const int*)am + erow + cb);
                const int4* lp = (const int4*)((const int*)al + erow + cb);
                int4 a0 = ap[0], a1 = ap[1], l0 = lp[0], l1 = lp[1];
                amv[0]=a0.x; amv[1]=a0.y; amv[2]=a0.z; amv[3]=a0.w;
                amv[4]=a1.x; amv[5]=a1.y; amv[6]=a1.z; amv[7]=a1.w;
                alv[0]=l0.x; alv[1]=l0.y; alv[2]=l0.z; alv[3]=l0.w;
                alv[4]=l1.x; alv[5]=l1.y; alv[6]=l1.z; alv[7]=l1.w;
            } else {
                uint2 au = *(const uint2*)(am + erow + cb);
                uint2 lu = *(const uint2*)(al + erow + cb);
                const unsigned char* ab = (const unsigned char*)&au;
                const unsigned char* lb = (const unsigned char*)&lu;
                #pragma unroll
                for (int c = 0; c < 8; c++){ amv[c] = ab[c]; alv[c] = lb[c]; }
            }
            // coords for 8 cols: 16 floats = 4 float4 (L1-broadcast across sharing threads)
            float4 ck4[4];
            #pragma unroll
            for (int i = 0; i < 4; i++)
                ck4[i] = __ldg((const float4*)(ck + ((size_t)(b*KK2 + cb))*2) + i);
            const float2* ckp = (const float2*)&ck4[0];

            float wv[8];
            #pragma unroll
            for (int c = 0; c < 8; c++){
                __nv_bfloat162 e2 = *(__nv_bfloat162*)&ew[c>>1];
                float e = __bfloat162float((c & 1) ? e2.y : e2.x) * li;
                float dx = cqv.x - ckp[c].x;
                float dy = cqv.y - ckp[c].y;
                float r2 = fmaxf(dx*dx + dy*dy, 1e-30f);
                float d  = alv[c] ? 0.f : (r2 * frsqrt2(r2) * bsc);
                float w  = amv[c] ? 0.f : (e - d);
                wv[c] = __uint_as_float(to_tf32(w));
            }
            float* wd = Wb + brow*WPAD + bc0 + 8*h;
            *(float4*)(wd)     = make_float4(wv[0], wv[1], wv[2], wv[3]);
            *(float4*)(wd + 4) = make_float4(wv[4], wv[5], wv[6], wv[7]);
        }
        __syncthreads();

        // ---- mma: A frags from Wb (4x LDS.32, conflict-free), B from g_Vp ----
        const float* Bb = g_Vp + ((size_t)((b*8 + wc)*32 + kt))*4096;
        #pragma unroll
        for (int ks = 0; ks < 8; ks++){
            unsigned Af[4][4];
            #pragma unroll
            for (int mf = 0; mf < 4; mf++){
                #pragma unroll
                for (int r = 0; r < 4; r++){
                    int row = mf*16 + g + 8*(r & 1);
                    int col = ks*8 + t + 4*(r >> 1);
                    Af[mf][r] = __float_as_uint(Wb[row*WPAD + col]);
                }
            }
            uint2 Bf[8];
            #pragma unroll
            for (int nf = 0; nf < 8; nf++)
                Bf[nf] = *(const uint2*)(Bb + ((ks*8 + nf)*32 + lane)*2);
            #pragma unroll
            for (int mf = 0; mf < 4; mf++)
                #pragma unroll
                for (int nf = 0; nf < 8; nf++)
                    mma_tf32(C[mf][nf], Af[mf], (const unsigned*)&Bf[nf]);
        }
        // no second sync needed: next build writes the other buffer; the kt+1 sync
        // transitively orders mma(kt) before build(kt+2).
    }

    // ---- epilogue ----
    #pragma unroll
    for (int mf = 0; mf < 4; mf++)
        #pragma unroll
        for (int rh = 0; rh < 2; rh++){
            int row = qt*64 + mf*16 + g + 8*rh;
            float* orow = out + ((size_t)(b*QQ + row))*FVV;
            #pragma unroll
            for (int nf = 0; nf < 8; nf++){
                int fv = wc*64 + nf*8 + 2*t;
                *(float2*)(orow + fv) = make_float2(C[mf][nf][rh*2+0], C[mf][nf][rh*2+1]);
            }
        }
}

extern "C" void kernel_launch(void* const* d_in, const int* in_sizes, int n_in,
                              void* d_out, int out_size)
{
    const float*         q    = (const float*)d_in[0];
    const float*         k    = (const float*)d_in[1];
    const float*         v    = (const float*)d_in[2];
    const float*         cq   = (const float*)d_in[3];
    const float*         ck   = (const float*)d_in[4];
    const unsigned char* am   = (const unsigned char*)d_in[5];
    const unsigned char* al   = (const unsigned char*)d_in[6];
    const float*         bias = (const float*)d_in[7];
    float*               out  = (float*)d_out;

    static int smem_set = 0;
    if (!smem_set){
        cudaFuncSetAttribute(pass1_kernel, cudaFuncAttributeMaxDynamicSharedMemorySize, 68096);
        cudaFuncSetAttribute(pass2_kernel, cudaFuncAttributeMaxDynamicSharedMemorySize, 34816);
        smem_set = 1;
    }

    detect_mask_kernel<<<1, 1>>>(am);
    prep_qb_kernel<<<4096,  NTHREADS>>>(q);
    prep_kb_kernel<<<8192,  NTHREADS>>>(k);
    prep_v_kernel <<<16384, NTHREADS>>>(v);
    pass1_kernel<<<256, NTHREADS, 68096>>>();
    pass2_kernel<<<256, NTHREADS, 34816>>>(out, cq, ck, am, al, bias);
}